// round 12
// baseline (speedup 1.0000x reference)
#include <cuda_runtime.h>
#include <cuda_bf16.h>
#include <math.h>
#include <stdint.h>

// ---------------- problem constants ----------------
#define BB   64
#define SS   64
#define TT   32
#define EE   512
#define UU   1024
#define G4   (4*UU)      // 4096
#define U2   (2*UU)      // 2048
#define VD_  32000
#define NSTEP (SS+TT)    // 96
#define NCTA 192

// ---------------- device scratch (allocation-free contract) ----------------
__device__ __nv_bfloat16 g_XembEHi[BB*SS*EE];
__device__ __nv_bfloat16 g_XembELo[BB*SS*EE];
__device__ __nv_bfloat16 g_XembDHi[BB*TT*EE];
__device__ __nv_bfloat16 g_XembDLo[BB*TT*EE];
__device__ __nv_bfloat16 g_WeHi[G4*EE];
__device__ __nv_bfloat16 g_WeLo[G4*EE];
__device__ __nv_bfloat16 g_WidHi[G4*EE];
__device__ __nv_bfloat16 g_WidLo[G4*EE];
__device__ __nv_bfloat16 g_WdHi[(size_t)VD_*U2];
__device__ __nv_bfloat16 g_WdLo[(size_t)VD_*U2];
__device__ __nv_bfloat16 g_hcHi[(size_t)BB*TT*U2];
__device__ __nv_bfloat16 g_hcLo[(size_t)BB*TT*U2];

// recurrence: reordered bf16 weights (CTA-sliced, gate-interleaved rows)
__device__ __nv_bfloat16 g_WreHi[(size_t)G4*UU];          // enc: row' = cta*32 + g*8 + uu
__device__ __nv_bfloat16 g_WreLo[(size_t)G4*UU];
__device__ __nv_bfloat16 g_WrdHi[(size_t)(UU+G4)*UU];     // dec: row' = cta*40 + [q:0..7 | 8+g*8+uu]
__device__ __nv_bfloat16 g_WrdLo[(size_t)(UU+G4)*UU];
// h double-buffered by step parity: read [par], write [par^1]
__device__ __nv_bfloat16 g_hHi[2][BB*UU];
__device__ __nv_bfloat16 g_hLo[2][BB*UU];

__device__ float g_Xe[(size_t)BB*SS*G4];            // x@W_ih_e^T + biases
__device__ float g_Xd[(size_t)BB*TT*G4];
__device__ float g_o [(size_t)BB*SS*UU];            // encoder outputs (fp32, for attention)
__device__ float g_c [BB*UU];
__device__ float g_q [2][BB*UU];                    // double-buffered q = h@Wa^T

// grid barrier state (persistent kernel)
__device__ unsigned g_cnt = 0;
__device__ unsigned g_epoch = 0;

// ---------------- helpers ----------------
__device__ __forceinline__ float sigf(float x) { return 1.f / (1.f + expf(-x)); }

__device__ __forceinline__ void cp16(void* dst, const void* src) {
    uint32_t a;
    asm("{ .reg .u64 t; cvta.to.shared.u64 t, %1; cvt.u32.u64 %0, t; }"
        : "=r"(a) : "l"(dst));
    asm volatile("cp.async.cg.shared.global [%0], [%1], 16;" :: "r"(a), "l"(src));
}

__device__ __forceinline__ void mma16816(float* c, const uint32_t* a, const uint32_t* b) {
    asm volatile(
        "mma.sync.aligned.m16n8k16.row.col.f32.bf16.bf16.f32 "
        "{%0,%1,%2,%3}, {%4,%5,%6,%7}, {%8,%9}, {%0,%1,%2,%3};"
        : "+f"(c[0]), "+f"(c[1]), "+f"(c[2]), "+f"(c[3])
        : "r"(a[0]), "r"(a[1]), "r"(a[2]), "r"(a[3]), "r"(b[0]), "r"(b[1]));
}

__device__ __forceinline__ void split1(float x, __nv_bfloat16& h, __nv_bfloat16& l) {
    h = __float2bfloat16(x);
    l = __float2bfloat16(x - __bfloat162float(h));
}

// ---------------- generic fp32 -> bf16 hi/lo split ----------------
__global__ void k_split4(const float4* __restrict__ src,
                         __nv_bfloat162* __restrict__ hi,
                         __nv_bfloat162* __restrict__ lo, int n4)
{
    int gid = blockIdx.x * blockDim.x + threadIdx.x;
    if (gid >= n4) return;
    float4 v = src[gid];
    __nv_bfloat16 hx, hy, hz, hw, lx, ly, lz, lw;
    split1(v.x, hx, lx); split1(v.y, hy, ly);
    split1(v.z, hz, lz); split1(v.w, hw, lw);
    __nv_bfloat162 a; a.x = hx; a.y = hy;
    __nv_bfloat162 b; b.x = hz; b.y = hw;
    __nv_bfloat162 c; c.x = lx; c.y = ly;
    __nv_bfloat162 d; d.x = lz; d.y = lw;
    hi[gid * 2] = a; hi[gid * 2 + 1] = b;
    lo[gid * 2] = c; lo[gid * 2 + 1] = d;
}

// ---------------- reorder + split for recurrence weights ----------------
__global__ void k_split_reord_enc(const float4* __restrict__ W) {
    int gid = blockIdx.x * blockDim.x + threadIdx.x;   // G4 * 256
    int rp = gid >> 8, c = gid & 255;
    int cta = rp >> 5, rr = rp & 31;
    int g = rr >> 3, uu = rr & 7;
    int orig = g * UU + cta * 8 + uu;
    float4 v = W[(size_t)orig * 256 + c];
    __nv_bfloat16 hx, hy, hz, hw, lx, ly, lz, lw;
    split1(v.x, hx, lx); split1(v.y, hy, ly);
    split1(v.z, hz, lz); split1(v.w, hw, lw);
    __nv_bfloat162 a; a.x = hx; a.y = hy;
    __nv_bfloat162 b; b.x = hz; b.y = hw;
    __nv_bfloat162 cc; cc.x = lx; cc.y = ly;
    __nv_bfloat162 dd; dd.x = lz; dd.y = lw;
    ((__nv_bfloat162*)g_WreHi)[gid * 2] = a; ((__nv_bfloat162*)g_WreHi)[gid * 2 + 1] = b;
    ((__nv_bfloat162*)g_WreLo)[gid * 2] = cc; ((__nv_bfloat162*)g_WreLo)[gid * 2 + 1] = dd;
}

__global__ void k_split_reord_dec(const float4* __restrict__ Wa,
                                  const float4* __restrict__ Whh) {
    int gid = blockIdx.x * blockDim.x + threadIdx.x;   // (UU+G4) * 256
    int rp = gid >> 8, c = gid & 255;
    int cta = rp / 40, rr = rp % 40;
    const float4* src;
    int orig;
    if (rr < 8) { src = Wa;  orig = cta * 8 + rr; }
    else {
        int g = (rr - 8) >> 3, uu = (rr - 8) & 7;
        src = Whh; orig = g * UU + cta * 8 + uu;
    }
    float4 v = src[(size_t)orig * 256 + c];
    __nv_bfloat16 hx, hy, hz, hw, lx, ly, lz, lw;
    split1(v.x, hx, lx); split1(v.y, hy, ly);
    split1(v.z, hz, lz); split1(v.w, hw, lw);
    __nv_bfloat162 a; a.x = hx; a.y = hy;
    __nv_bfloat162 b; b.x = hz; b.y = hw;
    __nv_bfloat162 cc; cc.x = lx; cc.y = ly;
    __nv_bfloat162 dd; dd.x = lz; dd.y = lw;
    ((__nv_bfloat162*)g_WrdHi)[gid * 2] = a; ((__nv_bfloat162*)g_WrdHi)[gid * 2 + 1] = b;
    ((__nv_bfloat162*)g_WrdLo)[gid * 2] = cc; ((__nv_bfloat162*)g_WrdLo)[gid * 2 + 1] = dd;
}

// ---------------- embedding gathers (write bf16 hi/lo) ----------------
__global__ void k_gather_enc(const int* __restrict__ x, const float* __restrict__ emb) {
    int gid = blockIdx.x * blockDim.x + threadIdx.x;      // BB*SS*(EE/4)
    const int E4 = EE / 4;
    int r = gid / E4, c = gid % E4;
    float4 v = ((const float4*)emb)[(size_t)x[r] * E4 + c];
    __nv_bfloat16 hx, hy, hz, hw, lx, ly, lz, lw;
    split1(v.x, hx, lx); split1(v.y, hy, ly);
    split1(v.z, hz, lz); split1(v.w, hw, lw);
    size_t pi = (size_t)r * (EE / 2) + c * 2;
    __nv_bfloat162 a; a.x = hx; a.y = hy; ((__nv_bfloat162*)g_XembEHi)[pi] = a;
    __nv_bfloat162 b; b.x = hz; b.y = hw; ((__nv_bfloat162*)g_XembEHi)[pi + 1] = b;
    __nv_bfloat162 cc; cc.x = lx; cc.y = ly; ((__nv_bfloat162*)g_XembELo)[pi] = cc;
    __nv_bfloat162 dd; dd.x = lz; dd.y = lw; ((__nv_bfloat162*)g_XembELo)[pi + 1] = dd;
}

__global__ void k_gather_dec(const int* __restrict__ y, const float* __restrict__ emb) {
    int gid = blockIdx.x * blockDim.x + threadIdx.x;      // BB*TT*(EE/4)
    const int E4 = EE / 4;
    int r = gid / E4, c = gid % E4;
    int b = r / TT, t = r % TT;
    int id = y[b * (TT + 1) + t];
    float4 v = ((const float4*)emb)[(size_t)id * E4 + c];
    __nv_bfloat16 hx, hy, hz, hw, lx, ly, lz, lw;
    split1(v.x, hx, lx); split1(v.y, hy, ly);
    split1(v.z, hz, lz); split1(v.w, hw, lw);
    size_t pi = (size_t)r * (EE / 2) + c * 2;
    __nv_bfloat162 a; a.x = hx; a.y = hy; ((__nv_bfloat162*)g_XembDHi)[pi] = a;
    __nv_bfloat162 b2; b2.x = hz; b2.y = hw; ((__nv_bfloat162*)g_XembDHi)[pi + 1] = b2;
    __nv_bfloat162 cc; cc.x = lx; cc.y = ly; ((__nv_bfloat162*)g_XembDLo)[pi] = cc;
    __nv_bfloat162 dd; dd.x = lz; dd.y = lw; ((__nv_bfloat162*)g_XembDLo)[pi + 1] = dd;
}

__global__ void k_init_state() {
    int gid = blockIdx.x * blockDim.x + threadIdx.x;
    if (gid < BB * UU) {
        g_c[gid] = 0.f;
        g_hHi[0][gid] = __float2bfloat16(0.f);
        g_hLo[0][gid] = __float2bfloat16(0.f);
        g_hHi[1][gid] = __float2bfloat16(0.f);
        g_hLo[1][gid] = __float2bfloat16(0.f);
    }
}

// ---------------- HMMA bf16x2-compensated GEMM (big, 128x128 tile) ----------------
#define PITCH   80
#define ARR_SZ  (128 * PITCH)           // 10240
#define STG_SZ  (4 * ARR_SZ)            // 40960
#define OFF_AHI 0
#define OFF_ALO ARR_SZ
#define OFF_BHI (2 * ARR_SZ)
#define OFF_BLO (3 * ARR_SZ)
#define SMEM_DYN (2 * STG_SZ)           // 80 KB

template <int MODE>
__global__ void __launch_bounds__(256)
k_hmma(const __nv_bfloat16* __restrict__ Ahi, const __nv_bfloat16* __restrict__ Alo,
       const __nv_bfloat16* __restrict__ Bhi, const __nv_bfloat16* __restrict__ Blo,
       const float* __restrict__ bias1, const float* __restrict__ bias2,
       float* __restrict__ C, int M, int N, int K)
{
    extern __shared__ __align__(16) char smem[];

    const int tid = threadIdx.x;
    const int wid = tid >> 5, lane = tid & 31;
    const int gq = lane >> 2, tq = lane & 3;
    const int wm = (wid >> 2) * 64;
    const int wn = (wid & 3) * 32;
    const int bm = blockIdx.y * 128, bn = blockIdx.x * 128;
    const int nk = K >> 5;

    const __nv_bfloat16* gsrc[4] = {Ahi, Alo, Bhi, Blo};

    auto load_stage = [&](int kc) {
        char* base = smem + (kc & 1) * STG_SZ;
        int k0 = kc << 5;
#pragma unroll
        for (int i = 0; i < 8; i++) {
            int e = tid + i * 256;
            int arr = e >> 9;
            int r = (e >> 2) & 127;
            int seg = e & 3;
            int grow = (arr < 2 ? bm : bn) + r;
            const __nv_bfloat16* src = gsrc[arr] + (size_t)grow * K + k0 + seg * 8;
            cp16(base + arr * ARR_SZ + r * PITCH + seg * 16, src);
        }
        asm volatile("cp.async.commit_group;");
    };

    float acc[4][4][4];
#pragma unroll
    for (int i = 0; i < 4; i++)
#pragma unroll
        for (int j = 0; j < 4; j++)
#pragma unroll
            for (int q = 0; q < 4; q++) acc[i][j][q] = 0.f;

    load_stage(0);

    for (int kc = 0; kc < nk; kc++) {
        if (kc + 1 < nk) {
            load_stage(kc + 1);
            asm volatile("cp.async.wait_group 1;");
        } else {
            asm volatile("cp.async.wait_group 0;");
        }
        __syncthreads();

        const char* base = smem + (kc & 1) * STG_SZ;
#pragma unroll
        for (int kk = 0; kk < 2; kk++) {
            const int kb = kk * 32;
            uint32_t ah[4][4], al[4][4], bh[4][2], bl[4][2];
#pragma unroll
            for (int i = 0; i < 4; i++) {
                int r0 = wm + i * 16 + gq;
                const char* pa = base + kb + 4 * tq;
                ah[i][0] = *(const uint32_t*)(pa + OFF_AHI + r0 * PITCH);
                ah[i][1] = *(const uint32_t*)(pa + OFF_AHI + (r0 + 8) * PITCH);
                ah[i][2] = *(const uint32_t*)(pa + OFF_AHI + r0 * PITCH + 16);
                ah[i][3] = *(const uint32_t*)(pa + OFF_AHI + (r0 + 8) * PITCH + 16);
                al[i][0] = *(const uint32_t*)(pa + OFF_ALO + r0 * PITCH);
                al[i][1] = *(const uint32_t*)(pa + OFF_ALO + (r0 + 8) * PITCH);
                al[i][2] = *(const uint32_t*)(pa + OFF_ALO + r0 * PITCH + 16);
                al[i][3] = *(const uint32_t*)(pa + OFF_ALO + (r0 + 8) * PITCH + 16);
            }
#pragma unroll
            for (int j = 0; j < 4; j++) {
                int rb = wn + j * 8 + gq;
                const char* pb = base + kb + 4 * tq;
                bh[j][0] = *(const uint32_t*)(pb + OFF_BHI + rb * PITCH);
                bh[j][1] = *(const uint32_t*)(pb + OFF_BHI + rb * PITCH + 16);
                bl[j][0] = *(const uint32_t*)(pb + OFF_BLO + rb * PITCH);
                bl[j][1] = *(const uint32_t*)(pb + OFF_BLO + rb * PITCH + 16);
            }
#pragma unroll
            for (int i = 0; i < 4; i++)
#pragma unroll
                for (int j = 0; j < 4; j++) {
                    mma16816(acc[i][j], ah[i], bh[j]);
                    mma16816(acc[i][j], ah[i], bl[j]);
                    mma16816(acc[i][j], al[i], bh[j]);
                }
        }
        __syncthreads();
    }

#pragma unroll
    for (int i = 0; i < 4; i++) {
        int r0 = bm + wm + i * 16 + gq;
        if (MODE == 0) {
#pragma unroll
            for (int j = 0; j < 4; j++) {
                int col = bn + wn + j * 8 + 2 * tq;
                float b0 = bias1[col] + (bias2 ? bias2[col] : 0.f);
                float b1 = bias1[col + 1] + (bias2 ? bias2[col + 1] : 0.f);
                float2 v0 = make_float2(acc[i][j][0] + b0, acc[i][j][1] + b1);
                float2 v1 = make_float2(acc[i][j][2] + b0, acc[i][j][3] + b1);
                *(float2*)(C + (size_t)r0 * N + col) = v0;
                *(float2*)(C + (size_t)(r0 + 8) * N + col) = v1;
            }
        } else {
            float bv0 = bias1[r0];
            float bv1 = bias1[r0 + 8];
#pragma unroll
            for (int j = 0; j < 4; j++) {
                int col = bn + wn + j * 8 + 2 * tq;
                int b = col >> 5, t = col & 31;
                float* p0 = C + ((size_t)b * VD_ + r0) * 32 + t;
                float* p1 = C + ((size_t)b * VD_ + r0 + 8) * 32 + t;
                *(float2*)p0 = make_float2(acc[i][j][0] + bv0, acc[i][j][1] + bv0);
                *(float2*)p1 = make_float2(acc[i][j][2] + bv1, acc[i][j][3] + bv1);
            }
        }
    }
}

// ---------------- attention body (writes ctx as bf16 hi/lo into hc) ----------------
__device__ __forceinline__ void attn_body(int b, int ta, const float* __restrict__ ba,
                                          float* scratch)
{
    float* qs = scratch;          // 1024
    float* sc = scratch + UU;     // 65 (sc[SS] holds 1/sum)
    int tid = threadIdx.x;

    const float* qrow = g_q[ta & 1] + (size_t)b * UU;
    for (int u = tid; u < UU; u += 256) qs[u] = qrow[u] + ba[u];
    __syncthreads();

    int w = tid >> 5, lane = tid & 31;
    const float* ob = g_o + (size_t)b * SS * UU;
    for (int s = w; s < SS; s += 8) {
        const float* os = ob + (size_t)s * UU;
        float acc = 0.f;
        for (int u = lane; u < UU; u += 32) acc = fmaf(qs[u], os[u], acc);
#pragma unroll
        for (int off = 16; off; off >>= 1) acc += __shfl_xor_sync(0xffffffffu, acc, off);
        if (lane == 0) sc[s] = acc;
    }
    __syncthreads();

    if (tid == 0) {
        float mx = sc[0];
#pragma unroll
        for (int s = 1; s < SS; s++) mx = fmaxf(mx, sc[s]);
        float sum = 0.f;
        for (int s = 0; s < SS; s++) { float e = expf(sc[s] - mx); sc[s] = e; sum += e; }
        sc[SS] = 1.f / sum;
    }
    __syncthreads();
    float inv = sc[SS];

    size_t rowb = (size_t)(b * TT + ta) * U2;
    for (int u = tid; u < UU; u += 256) {
        float acc = 0.f;
#pragma unroll 8
        for (int s = 0; s < SS; s++) acc = fmaf(sc[s] * inv, ob[(size_t)s * UU + u], acc);
        __nv_bfloat16 hh, hl; split1(acc, hh, hl);
        g_hcHi[rowb + u] = hh;
        g_hcLo[rowb + u] = hl;
    }
    __syncthreads();
}

// ---------------- persistent recurrence kernel ----------------
// Grid NCTA=192, 2 CTAs/SM resident. CTAs 0..127: fused GEMM+gate per step.
// CTAs 128..191: attention riders (decoder, step t-1) + tail. Grid barrier per step.
#define DSTG  (208 * 80)                      // 16640, stage stride (max NR=40)
#define PS_SMEM (4 * DSTG + 64 * 33 * 4)      // 75008

__device__ __forceinline__ void grid_bar(unsigned target) {
    __threadfence();
    __syncthreads();
    if (threadIdx.x == 0) {
        unsigned t = atomicAdd(&g_cnt, 1);
        if (t == NCTA - 1) {
            g_cnt = 0;
            __threadfence();
            atomicAdd(&g_epoch, 1);
        } else {
            volatile unsigned* ep = &g_epoch;
            while (*ep < target) { __nanosleep(64); }
            __threadfence();
        }
    }
    __syncthreads();
}

__global__ void __launch_bounds__(256, 2)
k_rec_all(const float* __restrict__ ba)
{
    extern __shared__ __align__(16) char dsm[];

    const int tid = threadIdx.x;
    const int cta = blockIdx.x;
    const int wid = tid >> 5, lane = tid & 31;
    const int gq = lane >> 2, tq = lane & 3;
    const int mh = wid >> 2, nc = wid & 3;
    constexpr int OALO = 64 * 80;             // 5120
    constexpr int OBHI = 128 * 80;            // 10240
    float* zs = (float*)(dsm + 4 * DSTG);

    unsigned e0 = 0;
    if (tid == 0) e0 = *(volatile unsigned*)&g_epoch;

    for (int s = 0; s < NSTEP; s++) {
        const bool enc = (s < SS);
        const int tt = enc ? s : s - SS;
        const int par = s & 1;

        if (cta < 128) {
            const int NR  = enc ? 32 : 40;
            const int TOT = 512 + NR * 8;
            const int BLO = NR * 80;          // B lo offset relative to OBHI
            const __nv_bfloat16* Whi = enc ? g_WreHi : g_WrdHi;
            const __nv_bfloat16* Wlo = enc ? g_WreLo : g_WrdLo;
            const __nv_bfloat16* hHi = g_hHi[par];
            const __nv_bfloat16* hLo = g_hLo[par];
            const size_t wbase = (size_t)cta * NR * UU;

            auto load_stage = [&](int kc) {
                char* base = dsm + (kc & 3) * DSTG;
                int k0 = kc << 5;
#pragma unroll
                for (int i = 0; i < 4; i++) {
                    int e = tid + i * 256;
                    if (e < TOT) {
                        const __nv_bfloat16* src; char* dst;
                        if (e < 512) {
                            int arr = e >> 8, r = (e >> 2) & 63, seg = e & 3;
                            src = (arr ? hLo : hHi) + r * UU + k0 + seg * 8;
                            dst = base + arr * OALO + r * 80 + seg * 16;
                        } else {
                            int e2 = e - 512;
                            int arr = e2 >= NR * 4;
                            int idx = e2 - arr * NR * 4;
                            int r = idx >> 2, seg = idx & 3;
                            src = (arr ? Wlo : Whi) + wbase + (size_t)r * UU + k0 + seg * 8;
                            dst = base + OBHI + arr * BLO + r * 80 + seg * 16;
                        }
                        cp16(dst, src);
                    }
                }
                asm volatile("cp.async.commit_group;");
            };

            float accz[2][4] = {};
            float accq[4] = {};

            load_stage(0);
            load_stage(1);
            load_stage(2);

            for (int kc = 0; kc < 32; kc++) {
                if (kc + 3 < 32) load_stage(kc + 3);
                else             asm volatile("cp.async.commit_group;");
                asm volatile("cp.async.wait_group 3;");
                __syncthreads();

                const char* base = dsm + (kc & 3) * DSTG;
#pragma unroll
                for (int kk = 0; kk < 2; kk++) {
                    const int kb = kk * 32;
                    const char* pa = base + kb + 4 * tq;
                    uint32_t ah[2][4], al[2][4];
#pragma unroll
                    for (int i = 0; i < 2; i++) {
                        int r0 = mh * 32 + i * 16 + gq;
                        ah[i][0] = *(const uint32_t*)(pa + r0 * 80);
                        ah[i][1] = *(const uint32_t*)(pa + (r0 + 8) * 80);
                        ah[i][2] = *(const uint32_t*)(pa + r0 * 80 + 16);
                        ah[i][3] = *(const uint32_t*)(pa + (r0 + 8) * 80 + 16);
                        al[i][0] = *(const uint32_t*)(pa + OALO + r0 * 80);
                        al[i][1] = *(const uint32_t*)(pa + OALO + (r0 + 8) * 80);
                        al[i][2] = *(const uint32_t*)(pa + OALO + r0 * 80 + 16);
                        al[i][3] = *(const uint32_t*)(pa + OALO + (r0 + 8) * 80 + 16);
                    }
                    {   // z tile: B row = (enc?0:8) + nc*8 + gq
                        int rb = (enc ? 0 : 8) + nc * 8 + gq;
                        const char* pb = base + OBHI + rb * 80 + kb + 4 * tq;
                        uint32_t bh[2], bl[2];
                        bh[0] = *(const uint32_t*)(pb);
                        bh[1] = *(const uint32_t*)(pb + 16);
                        bl[0] = *(const uint32_t*)(pb + BLO);
                        bl[1] = *(const uint32_t*)(pb + BLO + 16);
#pragma unroll
                        for (int i = 0; i < 2; i++) {
                            mma16816(accz[i], ah[i], bh);
                            mma16816(accz[i], ah[i], bl);
                            mma16816(accz[i], al[i], bh);
                        }
                    }
                    if (!enc && nc < 2) {   // q tile: B rows 0..7, A frag = ah[nc]
                        const char* pb = base + OBHI + gq * 80 + kb + 4 * tq;
                        uint32_t bh[2], bl[2];
                        bh[0] = *(const uint32_t*)(pb);
                        bh[1] = *(const uint32_t*)(pb + 16);
                        bl[0] = *(const uint32_t*)(pb + BLO);
                        bl[1] = *(const uint32_t*)(pb + BLO + 16);
                        mma16816(accq, ah[nc], bh);
                        mma16816(accq, ah[nc], bl);
                        mma16816(accq, al[nc], bh);
                    }
                }
                __syncthreads();
            }

            // ---- z -> SMEM ----
#pragma unroll
            for (int i = 0; i < 2; i++) {
                int b0 = mh * 32 + i * 16 + gq;
                int col = nc * 8 + 2 * tq;
                zs[b0 * 33 + col]           = accz[i][0];
                zs[b0 * 33 + col + 1]       = accz[i][1];
                zs[(b0 + 8) * 33 + col]     = accz[i][2];
                zs[(b0 + 8) * 33 + col + 1] = accz[i][3];
            }
            // ---- q -> global (decoder) ----
            if (!enc && nc < 2) {
                int f = mh * 2 + nc;
                int b0 = f * 16 + gq;
                int u0 = cta * 8 + 2 * tq;
                *(float2*)&g_q[tt & 1][b0 * UU + u0]       = make_float2(accq[0], accq[1]);
                *(float2*)&g_q[tt & 1][(b0 + 8) * UU + u0] = make_float2(accq[2], accq[3]);
            }
            __syncthreads();

            // ---- gate: 2 (b,uu) per thread ----
#pragma unroll
            for (int rep = 0; rep < 2; rep++) {
                int idx = tid + rep * 256;      // 0..511
                int b = idx >> 3, uu = idx & 7;
                int u = cta * 8 + uu;
                const float* xrow = enc ? (g_Xe + (size_t)(b * SS + tt) * G4)
                                        : (g_Xd + (size_t)(b * TT + tt) * G4);
                float zi = zs[b * 33 + uu]      + xrow[u];
                float zf = zs[b * 33 + 8 + uu]  + xrow[UU + u];
                float zg = zs[b * 33 + 16 + uu] + xrow[2 * UU + u];
                float zo = zs[b * 33 + 24 + uu] + xrow[3 * UU + u];
                float c = g_c[b * UU + u];
                float cn = sigf(zf) * c + sigf(zi) * tanhf(zg);
                float hn = sigf(zo) * tanhf(cn);
                g_c[b * UU + u] = cn;
                __nv_bfloat16 hh, hl; split1(hn, hh, hl);
                g_hHi[par ^ 1][b * UU + u] = hh;
                g_hLo[par ^ 1][b * UU + u] = hl;
                if (enc) {
                    g_o[(size_t)(b * SS + tt) * UU + u] = hn;
                } else {
                    size_t row = (size_t)(b * TT + tt) * U2 + UU + u;
                    g_hcHi[row] = hh;
                    g_hcLo[row] = hl;
                }
            }
        } else {
            // attention riders: during decoder, process step tt-1
            if (!enc && tt > 0)
                attn_body(cta - 128, tt - 1, ba, (float*)dsm);
        }

        grid_bar(e0 + (unsigned)(s + 1));
    }

    // tail attention for last decoder step
    if (cta >= 128)
        attn_body(cta - 128, TT - 1, ba, (float*)dsm);
}

// ---------------- launch ----------------
extern "C" void kernel_launch(void* const* d_in, const int* in_sizes, int n_in,
                              void* d_out, int out_size)
{
    const int*   x       = (const int*)d_in[0];
    const int*   y       = (const int*)d_in[1];
    const float* enc_emb = (const float*)d_in[2];
    const float* dec_emb = (const float*)d_in[3];
    const float* W_ih_e  = (const float*)d_in[4];
    const float* W_hh_e  = (const float*)d_in[5];
    const float* b_ih_e  = (const float*)d_in[6];
    const float* b_hh_e  = (const float*)d_in[7];
    const float* Wa      = (const float*)d_in[8];
    const float* ba      = (const float*)d_in[9];
    const float* W_ih_d  = (const float*)d_in[10];
    const float* W_hh_d  = (const float*)d_in[11];
    const float* b_ih_d  = (const float*)d_in[12];
    const float* b_hh_d  = (const float*)d_in[13];
    const float* Wd      = (const float*)d_in[14];
    const float* bd      = (const float*)d_in[15];
    float* out = (float*)d_out;

    float *pXe, *pXd;
    __nv_bfloat16 *pXeHi, *pXeLo, *pXdHi, *pXdLo, *pWeHi, *pWeLo, *pWidHi, *pWidLo;
    __nv_bfloat16 *pWdHi, *pWdLo, *pHcHi, *pHcLo;
    cudaGetSymbolAddress((void**)&pXe, g_Xe);
    cudaGetSymbolAddress((void**)&pXd, g_Xd);
    cudaGetSymbolAddress((void**)&pXeHi, g_XembEHi);
    cudaGetSymbolAddress((void**)&pXeLo, g_XembELo);
    cudaGetSymbolAddress((void**)&pXdHi, g_XembDHi);
    cudaGetSymbolAddress((void**)&pXdLo, g_XembDLo);
    cudaGetSymbolAddress((void**)&pWeHi, g_WeHi);
    cudaGetSymbolAddress((void**)&pWeLo, g_WeLo);
    cudaGetSymbolAddress((void**)&pWidHi, g_WidHi);
    cudaGetSymbolAddress((void**)&pWidLo, g_WidLo);
    cudaGetSymbolAddress((void**)&pWdHi, g_WdHi);
    cudaGetSymbolAddress((void**)&pWdLo, g_WdLo);
    cudaGetSymbolAddress((void**)&pHcHi, g_hcHi);
    cudaGetSymbolAddress((void**)&pHcLo, g_hcLo);

    cudaFuncSetAttribute(k_hmma<0>, cudaFuncAttributeMaxDynamicSharedMemorySize, SMEM_DYN);
    cudaFuncSetAttribute(k_hmma<1>, cudaFuncAttributeMaxDynamicSharedMemorySize, SMEM_DYN);
    cudaFuncSetAttribute(k_rec_all, cudaFuncAttributeMaxDynamicSharedMemorySize, PS_SMEM);

    // embeddings + init + weight splits
    k_gather_enc<<<BB * SS * (EE / 4) / 256, 256>>>(x, enc_emb);
    k_gather_dec<<<BB * TT * (EE / 4) / 256, 256>>>(y, dec_emb);
    k_init_state<<<BB * UU / 256, 256>>>();
    {
        int n4 = G4 * EE / 4;
        k_split4<<<(n4 + 255) / 256, 256>>>((const float4*)W_ih_e,
            (__nv_bfloat162*)pWeHi, (__nv_bfloat162*)pWeLo, n4);
        k_split4<<<(n4 + 255) / 256, 256>>>((const float4*)W_ih_d,
            (__nv_bfloat162*)pWidHi, (__nv_bfloat162*)pWidLo, n4);
    }
    // recurrence weights: reorder + split
    k_split_reord_enc<<<G4 * 256 / 256, 256>>>((const float4*)W_hh_e);
    k_split_reord_dec<<<(UU + G4) * 256 / 256, 256>>>((const float4*)Wa,
                                                      (const float4*)W_hh_d);
    {
        int n4 = (int)((size_t)VD_ * U2 / 4);
        k_split4<<<(n4 + 255) / 256, 256>>>((const float4*)Wd,
            (__nv_bfloat162*)pWdHi, (__nv_bfloat162*)pWdLo, n4);
    }

    // time-batched input projections (tensor pipe)
    k_hmma<0><<<dim3(G4 / 128, (BB * SS) / 128), 256, SMEM_DYN>>>(
        pXeHi, pXeLo, pWeHi, pWeLo, b_ih_e, b_hh_e, pXe, BB * SS, G4, EE);
    k_hmma<0><<<dim3(G4 / 128, (BB * TT) / 128), 256, SMEM_DYN>>>(
        pXdHi, pXdLo, pWidHi, pWidLo, b_ih_d, b_hh_d, pXd, BB * TT, G4, EE);

    // entire recurrence (enc + dec + attention): ONE persistent launch
    k_rec_all<<<NCTA, 256, PS_SMEM>>>(ba);

    // batched logits (A = Wd rows, B = hc rows, written bf16-split in-kernel)
    k_hmma<1><<<dim3((BB * TT) / 128, VD_ / 128), 256, SMEM_DYN>>>(
        pWdHi, pWdLo, pHcHi, pHcLo, bd, nullptr, out, VD_, BB * TT, U2);
}

// round 13
// speedup vs baseline: 1.2730x; 1.2730x over previous
#include <cuda_runtime.h>
#include <cuda_bf16.h>
#include <math.h>
#include <stdint.h>

// ---------------- problem constants ----------------
#define BB   64
#define SS   64
#define TT   32
#define EE   512
#define UU   1024
#define G4   (4*UU)      // 4096
#define U2   (2*UU)      // 2048
#define NC   (UU+G4)     // 5120 (Wa ‖ W_hh_d rows)
#define VD_  32000
#define RS   4           // recurrence K-split
#define RKC  (UU/RS)     // 256

// ---------------- device scratch (allocation-free contract) ----------------
__device__ __nv_bfloat16 g_XembEHi[BB*SS*EE];
__device__ __nv_bfloat16 g_XembELo[BB*SS*EE];
__device__ __nv_bfloat16 g_XembDHi[BB*TT*EE];
__device__ __nv_bfloat16 g_XembDLo[BB*TT*EE];
__device__ __nv_bfloat16 g_WeHi[G4*EE];
__device__ __nv_bfloat16 g_WeLo[G4*EE];
__device__ __nv_bfloat16 g_WidHi[G4*EE];
__device__ __nv_bfloat16 g_WidLo[G4*EE];
__device__ __nv_bfloat16 g_WdHi[(size_t)VD_*U2];
__device__ __nv_bfloat16 g_WdLo[(size_t)VD_*U2];
__device__ __nv_bfloat16 g_hcHi[(size_t)BB*TT*U2];   // [b*T+t][ctx|h] bf16 hi
__device__ __nv_bfloat16 g_hcLo[(size_t)BB*TT*U2];   // lo

// recurrence bf16 weights
__device__ __nv_bfloat16 g_WhheHi[(size_t)G4*UU];
__device__ __nv_bfloat16 g_WhheLo[(size_t)G4*UU];
__device__ __nv_bfloat16 g_WcatHi[(size_t)NC*UU];     // rows 0..1023 = Wa, 1024.. = W_hh_d
__device__ __nv_bfloat16 g_WcatLo[(size_t)NC*UU];
__device__ __nv_bfloat16 g_hHi[BB*UU];
__device__ __nv_bfloat16 g_hLo[BB*UU];

__device__ float g_Xe[(size_t)BB*SS*G4];            // x@W_ih_e^T + biases
__device__ float g_Xd[(size_t)BB*TT*G4];
__device__ float g_o [(size_t)BB*SS*UU];            // encoder outputs
__device__ float g_h [BB*UU];
__device__ float g_c [BB*UU];
__device__ float g_p [(size_t)RS*BB*NC];            // K-split partials

// ---------------- helpers ----------------
__device__ __forceinline__ float sigf(float x) { return 1.f / (1.f + expf(-x)); }

__device__ __forceinline__ void cp16(void* dst, const void* src) {
    uint32_t a;
    asm("{ .reg .u64 t; cvta.to.shared.u64 t, %1; cvt.u32.u64 %0, t; }"
        : "=r"(a) : "l"(dst));
    asm volatile("cp.async.cg.shared.global [%0], [%1], 16;" :: "r"(a), "l"(src));
}

__device__ __forceinline__ void mma16816(float* c, const uint32_t* a, const uint32_t* b) {
    asm volatile(
        "mma.sync.aligned.m16n8k16.row.col.f32.bf16.bf16.f32 "
        "{%0,%1,%2,%3}, {%4,%5,%6,%7}, {%8,%9}, {%0,%1,%2,%3};"
        : "+f"(c[0]), "+f"(c[1]), "+f"(c[2]), "+f"(c[3])
        : "r"(a[0]), "r"(a[1]), "r"(a[2]), "r"(a[3]), "r"(b[0]), "r"(b[1]));
}

__device__ __forceinline__ void split1(float x, __nv_bfloat16& h, __nv_bfloat16& l) {
    h = __float2bfloat16(x);
    l = __float2bfloat16(x - __bfloat162float(h));
}

// ---------------- fp32 -> bf16 hi/lo split (4x grid-stride unroll for MLP) ----------
__global__ void k_split4(const float4* __restrict__ src,
                         __nv_bfloat162* __restrict__ hi,
                         __nv_bfloat162* __restrict__ lo, int n4)
{
    int base = blockIdx.x * blockDim.x + threadIdx.x;
    int stride = gridDim.x * blockDim.x;
#pragma unroll
    for (int it = 0; it < 4; it++) {
        int gid = base + it * stride;
        if (gid < n4) {
            float4 v = src[gid];
            __nv_bfloat16 hx, hy, hz, hw, lx, ly, lz, lw;
            split1(v.x, hx, lx); split1(v.y, hy, ly);
            split1(v.z, hz, lz); split1(v.w, hw, lw);
            __nv_bfloat162 a; a.x = hx; a.y = hy;
            __nv_bfloat162 b; b.x = hz; b.y = hw;
            __nv_bfloat162 c; c.x = lx; c.y = ly;
            __nv_bfloat162 d; d.x = lz; d.y = lw;
            hi[gid * 2] = a; hi[gid * 2 + 1] = b;
            lo[gid * 2] = c; lo[gid * 2 + 1] = d;
        }
    }
}

// ---------------- embedding gathers (write bf16 hi/lo) ----------------
__global__ void k_gather_enc(const int* __restrict__ x, const float* __restrict__ emb) {
    int gid = blockIdx.x * blockDim.x + threadIdx.x;      // BB*SS*(EE/4)
    const int E4 = EE / 4;
    int r = gid / E4, c = gid % E4;
    float4 v = ((const float4*)emb)[(size_t)x[r] * E4 + c];
    __nv_bfloat16 hx, hy, hz, hw, lx, ly, lz, lw;
    split1(v.x, hx, lx); split1(v.y, hy, ly);
    split1(v.z, hz, lz); split1(v.w, hw, lw);
    size_t pi = (size_t)r * (EE / 2) + c * 2;
    __nv_bfloat162 a; a.x = hx; a.y = hy; ((__nv_bfloat162*)g_XembEHi)[pi] = a;
    __nv_bfloat162 b; b.x = hz; b.y = hw; ((__nv_bfloat162*)g_XembEHi)[pi + 1] = b;
    __nv_bfloat162 cc; cc.x = lx; cc.y = ly; ((__nv_bfloat162*)g_XembELo)[pi] = cc;
    __nv_bfloat162 dd; dd.x = lz; dd.y = lw; ((__nv_bfloat162*)g_XembELo)[pi + 1] = dd;
}

__global__ void k_gather_dec(const int* __restrict__ y, const float* __restrict__ emb) {
    int gid = blockIdx.x * blockDim.x + threadIdx.x;      // BB*TT*(EE/4)
    const int E4 = EE / 4;
    int r = gid / E4, c = gid % E4;
    int b = r / TT, t = r % TT;
    int id = y[b * (TT + 1) + t];
    float4 v = ((const float4*)emb)[(size_t)id * E4 + c];
    __nv_bfloat16 hx, hy, hz, hw, lx, ly, lz, lw;
    split1(v.x, hx, lx); split1(v.y, hy, ly);
    split1(v.z, hz, lz); split1(v.w, hw, lw);
    size_t pi = (size_t)r * (EE / 2) + c * 2;
    __nv_bfloat162 a; a.x = hx; a.y = hy; ((__nv_bfloat162*)g_XembDHi)[pi] = a;
    __nv_bfloat162 b2; b2.x = hz; b2.y = hw; ((__nv_bfloat162*)g_XembDHi)[pi + 1] = b2;
    __nv_bfloat162 cc; cc.x = lx; cc.y = ly; ((__nv_bfloat162*)g_XembDLo)[pi] = cc;
    __nv_bfloat162 dd; dd.x = lz; dd.y = lw; ((__nv_bfloat162*)g_XembDLo)[pi + 1] = dd;
}

__global__ void k_init_state() {
    int gid = blockIdx.x * blockDim.x + threadIdx.x;
    if (gid < BB * UU) {
        g_h[gid] = 0.f; g_c[gid] = 0.f;
        g_hHi[gid] = __float2bfloat16(0.f);
        g_hLo[gid] = __float2bfloat16(0.f);
    }
}

// ---------------- HMMA bf16x2-compensated GEMM (big, 128x128 tile) ----------------
#define PITCH   80
#define ARR_SZ  (128 * PITCH)           // 10240
#define STG_SZ  (4 * ARR_SZ)            // 40960
#define OFF_AHI 0
#define OFF_ALO ARR_SZ
#define OFF_BHI (2 * ARR_SZ)
#define OFF_BLO (3 * ARR_SZ)
#define SMEM_DYN (2 * STG_SZ)           // 80 KB

template <int MODE>
__global__ void __launch_bounds__(256)
k_hmma(const __nv_bfloat16* __restrict__ Ahi, const __nv_bfloat16* __restrict__ Alo,
       const __nv_bfloat16* __restrict__ Bhi, const __nv_bfloat16* __restrict__ Blo,
       const float* __restrict__ bias1, const float* __restrict__ bias2,
       float* __restrict__ C, int M, int N, int K)
{
    extern __shared__ __align__(16) char smem[];

    const int tid = threadIdx.x;
    const int wid = tid >> 5, lane = tid & 31;
    const int gq = lane >> 2, tq = lane & 3;
    const int wm = (wid >> 2) * 64;
    const int wn = (wid & 3) * 32;
    const int bm = blockIdx.y * 128, bn = blockIdx.x * 128;
    const int nk = K >> 5;

    const __nv_bfloat16* gsrc[4] = {Ahi, Alo, Bhi, Blo};

    auto load_stage = [&](int kc) {
        char* base = smem + (kc & 1) * STG_SZ;
        int k0 = kc << 5;
#pragma unroll
        for (int i = 0; i < 8; i++) {
            int e = tid + i * 256;
            int arr = e >> 9;
            int r = (e >> 2) & 127;
            int seg = e & 3;
            int grow = (arr < 2 ? bm : bn) + r;
            const __nv_bfloat16* src = gsrc[arr] + (size_t)grow * K + k0 + seg * 8;
            cp16(base + arr * ARR_SZ + r * PITCH + seg * 16, src);
        }
        asm volatile("cp.async.commit_group;");
    };

    float acc[4][4][4];
#pragma unroll
    for (int i = 0; i < 4; i++)
#pragma unroll
        for (int j = 0; j < 4; j++)
#pragma unroll
            for (int q = 0; q < 4; q++) acc[i][j][q] = 0.f;

    load_stage(0);

    for (int kc = 0; kc < nk; kc++) {
        if (kc + 1 < nk) {
            load_stage(kc + 1);
            asm volatile("cp.async.wait_group 1;");
        } else {
            asm volatile("cp.async.wait_group 0;");
        }
        __syncthreads();

        const char* base = smem + (kc & 1) * STG_SZ;
#pragma unroll
        for (int kk = 0; kk < 2; kk++) {
            const int kb = kk * 32;
            uint32_t ah[4][4], al[4][4], bh[4][2], bl[4][2];
#pragma unroll
            for (int i = 0; i < 4; i++) {
                int r0 = wm + i * 16 + gq;
                const char* pa = base + kb + 4 * tq;
                ah[i][0] = *(const uint32_t*)(pa + OFF_AHI + r0 * PITCH);
                ah[i][1] = *(const uint32_t*)(pa + OFF_AHI + (r0 + 8) * PITCH);
                ah[i][2] = *(const uint32_t*)(pa + OFF_AHI + r0 * PITCH + 16);
                ah[i][3] = *(const uint32_t*)(pa + OFF_AHI + (r0 + 8) * PITCH + 16);
                al[i][0] = *(const uint32_t*)(pa + OFF_ALO + r0 * PITCH);
                al[i][1] = *(const uint32_t*)(pa + OFF_ALO + (r0 + 8) * PITCH);
                al[i][2] = *(const uint32_t*)(pa + OFF_ALO + r0 * PITCH + 16);
                al[i][3] = *(const uint32_t*)(pa + OFF_ALO + (r0 + 8) * PITCH + 16);
            }
#pragma unroll
            for (int j = 0; j < 4; j++) {
                int rb = wn + j * 8 + gq;
                const char* pb = base + kb + 4 * tq;
                bh[j][0] = *(const uint32_t*)(pb + OFF_BHI + rb * PITCH);
                bh[j][1] = *(const uint32_t*)(pb + OFF_BHI + rb * PITCH + 16);
                bl[j][0] = *(const uint32_t*)(pb + OFF_BLO + rb * PITCH);
                bl[j][1] = *(const uint32_t*)(pb + OFF_BLO + rb * PITCH + 16);
            }
#pragma unroll
            for (int i = 0; i < 4; i++)
#pragma unroll
                for (int j = 0; j < 4; j++) {
                    mma16816(acc[i][j], ah[i], bh[j]);
                    mma16816(acc[i][j], ah[i], bl[j]);
                    mma16816(acc[i][j], al[i], bh[j]);
                }
        }
        __syncthreads();
    }

#pragma unroll
    for (int i = 0; i < 4; i++) {
        int r0 = bm + wm + i * 16 + gq;
        if (MODE == 0) {
#pragma unroll
            for (int j = 0; j < 4; j++) {
                int col = bn + wn + j * 8 + 2 * tq;
                float b0 = bias1[col] + (bias2 ? bias2[col] : 0.f);
                float b1 = bias1[col + 1] + (bias2 ? bias2[col + 1] : 0.f);
                float2 v0 = make_float2(acc[i][j][0] + b0, acc[i][j][1] + b1);
                float2 v1 = make_float2(acc[i][j][2] + b0, acc[i][j][3] + b1);
                *(float2*)(C + (size_t)r0 * N + col) = v0;
                *(float2*)(C + (size_t)(r0 + 8) * N + col) = v1;
            }
        } else {
            float bv0 = bias1[r0];
            float bv1 = bias1[r0 + 8];
#pragma unroll
            for (int j = 0; j < 4; j++) {
                int col = bn + wn + j * 8 + 2 * tq;
                int b = col >> 5, t = col & 31;
                float* p0 = C + ((size_t)b * VD_ + r0) * 32 + t;
                float* p1 = C + ((size_t)b * VD_ + r0 + 8) * 32 + t;
                *(float2*)p0 = make_float2(acc[i][j][0] + bv0, acc[i][j][1] + bv0);
                *(float2*)p1 = make_float2(acc[i][j][2] + bv1, acc[i][j][3] + bv1);
            }
        }
    }
}

// ---------------- HMMA recurrence GEMM: P[ks][64][N] = h[64,1024]@W[N,1024]^T chunk ----
// 64x128 tile, BK=32, K-chunk 256 (RS=4 splits), 8 warps (2x4), warp tile 32x32.
#define RA_SZ  (64 * PITCH)             // 5120
#define RB_SZ  (128 * PITCH)            // 10240
#define RST_SZ (2 * RA_SZ + 2 * RB_SZ)  // 30720
#define ROFF_ALO RA_SZ
#define ROFF_BHI (2 * RA_SZ)
#define ROFF_BLO (2 * RA_SZ + RB_SZ)
#define RSMEM_DYN (2 * RST_SZ)          // 61440

__global__ void __launch_bounds__(256)
k_hmma_rec(const __nv_bfloat16* __restrict__ Ahi, const __nv_bfloat16* __restrict__ Alo,
           const __nv_bfloat16* __restrict__ Bhi, const __nv_bfloat16* __restrict__ Blo,
           float* __restrict__ P, int N)
{
    extern __shared__ __align__(16) char smem[];

    const int tid = threadIdx.x;
    const int wid = tid >> 5, lane = tid & 31;
    const int gq = lane >> 2, tq = lane & 3;
    const int wm = (wid >> 2) * 32;               // 0,32
    const int wn = (wid & 3) * 32;                // 0..96
    const int bn = blockIdx.x * 128;
    const int ks = blockIdx.y;
    const int kbase = ks * RKC;

    auto load_stage = [&](int kc) {
        char* base = smem + (kc & 1) * RST_SZ;
        int k0 = kbase + (kc << 5);
#pragma unroll
        for (int i = 0; i < 6; i++) {
            int e = tid + i * 256;                // 0..1535
            const __nv_bfloat16* src;
            char* dst;
            if (e < 512) {                        // A hi/lo: 64 rows x 4 segs
                int arr = e >> 8;
                int r = (e >> 2) & 63, seg = e & 3;
                src = (arr ? Alo : Ahi) + (size_t)r * UU + k0 + seg * 8;
                dst = base + arr * RA_SZ + r * PITCH + seg * 16;
            } else {                              // B hi/lo: 128 rows x 4 segs
                int e2 = e - 512;
                int arr = e2 >> 9;
                int r = (e2 >> 2) & 127, seg = e2 & 3;
                src = (arr ? Blo : Bhi) + (size_t)(bn + r) * UU + k0 + seg * 8;
                dst = base + ROFF_BHI + arr * RB_SZ + r * PITCH + seg * 16;
            }
            cp16(dst, src);
        }
        asm volatile("cp.async.commit_group;");
    };

    float acc[2][4][4];
#pragma unroll
    for (int i = 0; i < 2; i++)
#pragma unroll
        for (int j = 0; j < 4; j++)
#pragma unroll
            for (int q = 0; q < 4; q++) acc[i][j][q] = 0.f;

    const int nk = RKC >> 5;                      // 8
    load_stage(0);

    for (int kc = 0; kc < nk; kc++) {
        if (kc + 1 < nk) {
            load_stage(kc + 1);
            asm volatile("cp.async.wait_group 1;");
        } else {
            asm volatile("cp.async.wait_group 0;");
        }
        __syncthreads();

        const char* base = smem + (kc & 1) * RST_SZ;
#pragma unroll
        for (int kk = 0; kk < 2; kk++) {
            const int kb = kk * 32;
            uint32_t ah[2][4], al[2][4], bh[4][2], bl[4][2];
#pragma unroll
            for (int i = 0; i < 2; i++) {
                int r0 = wm + i * 16 + gq;
                const char* pa = base + kb + 4 * tq;
                ah[i][0] = *(const uint32_t*)(pa + r0 * PITCH);
                ah[i][1] = *(const uint32_t*)(pa + (r0 + 8) * PITCH);
                ah[i][2] = *(const uint32_t*)(pa + r0 * PITCH + 16);
                ah[i][3] = *(const uint32_t*)(pa + (r0 + 8) * PITCH + 16);
                al[i][0] = *(const uint32_t*)(pa + ROFF_ALO + r0 * PITCH);
                al[i][1] = *(const uint32_t*)(pa + ROFF_ALO + (r0 + 8) * PITCH);
                al[i][2] = *(const uint32_t*)(pa + ROFF_ALO + r0 * PITCH + 16);
                al[i][3] = *(const uint32_t*)(pa + ROFF_ALO + (r0 + 8) * PITCH + 16);
            }
#pragma unroll
            for (int j = 0; j < 4; j++) {
                int rb = wn + j * 8 + gq;
                const char* pb = base + kb + 4 * tq;
                bh[j][0] = *(const uint32_t*)(pb + ROFF_BHI + rb * PITCH);
                bh[j][1] = *(const uint32_t*)(pb + ROFF_BHI + rb * PITCH + 16);
                bl[j][0] = *(const uint32_t*)(pb + ROFF_BLO + rb * PITCH);
                bl[j][1] = *(const uint32_t*)(pb + ROFF_BLO + rb * PITCH + 16);
            }
#pragma unroll
            for (int i = 0; i < 2; i++)
#pragma unroll
                for (int j = 0; j < 4; j++) {
                    mma16816(acc[i][j], ah[i], bh[j]);
                    mma16816(acc[i][j], ah[i], bl[j]);
                    mma16816(acc[i][j], al[i], bh[j]);
                }
        }
        __syncthreads();
    }

#pragma unroll
    for (int i = 0; i < 2; i++) {
        int r0 = wm + i * 16 + gq;
#pragma unroll
        for (int j = 0; j < 4; j++) {
            int col = bn + wn + j * 8 + 2 * tq;
            float* p0 = P + ((size_t)(ks * BB) + r0) * N + col;
            float* p1 = P + ((size_t)(ks * BB) + r0 + 8) * N + col;
            *(float2*)p0 = make_float2(acc[i][j][0], acc[i][j][1]);
            *(float2*)p1 = make_float2(acc[i][j][2], acc[i][j][3]);
        }
    }
}

// ---------------- encoder LSTM pointwise step ----------------
__global__ void k_enc_gate(int t)
{
    int gid = blockIdx.x * blockDim.x + threadIdx.x;
    int b = gid >> 10, u = gid & 1023;
    const float* xe = g_Xe + (size_t)(b * SS + t) * G4;
    float z[4];
#pragma unroll
    for (int gI = 0; gI < 4; gI++) {
        int col = gI * UU + u;
        float v = xe[col];
#pragma unroll
        for (int ks = 0; ks < RS; ks++) v += g_p[((size_t)ks * BB + b) * G4 + col];
        z[gI] = v;
    }
    float cprev = g_c[gid];
    float cn = sigf(z[1]) * cprev + sigf(z[0]) * tanhf(z[2]);
    float hn = sigf(z[3]) * tanhf(cn);
    g_c[gid] = cn;
    g_h[gid] = hn;
    __nv_bfloat16 hh, hl; split1(hn, hh, hl);
    g_hHi[gid] = hh; g_hLo[gid] = hl;
    g_o[(size_t)(b * SS + t) * UU + u] = hn;
}

// ---------------- fused decoder step: attention (blocks 0..63) + gate (blocks 64..319) ----
__global__ void __launch_bounds__(256)
k_dec_fused(int t, const float* __restrict__ ba)
{
    __shared__ float qs[UU];
    __shared__ float sc[SS];
    __shared__ float sinv;

    int tid = threadIdx.x;

    if (blockIdx.x < BB) {
        // ---------- attention for batch b (ctx -> hc bf16 hi/lo directly) ----------
        int b = blockIdx.x;
        for (int u = tid; u < UU; u += 256) {
            float v = ba[u];
#pragma unroll
            for (int ks = 0; ks < RS; ks++) v += g_p[((size_t)ks * BB + b) * NC + u];
            qs[u] = v;
        }
        __syncthreads();

        int w = tid >> 5, lane = tid & 31;
        const float* ob = g_o + (size_t)b * SS * UU;
        for (int s = w; s < SS; s += 8) {
            const float* os = ob + (size_t)s * UU;
            float acc = 0.f;
            for (int u = lane; u < UU; u += 32) acc = fmaf(qs[u], os[u], acc);
#pragma unroll
            for (int off = 16; off; off >>= 1) acc += __shfl_xor_sync(0xffffffffu, acc, off);
            if (lane == 0) sc[s] = acc;
        }
        __syncthreads();

        if (tid == 0) {
            float mx = sc[0];
#pragma unroll
            for (int s = 1; s < SS; s++) mx = fmaxf(mx, sc[s]);
            float sum = 0.f;
            for (int s = 0; s < SS; s++) { float e = expf(sc[s] - mx); sc[s] = e; sum += e; }
            sinv = 1.f / sum;
        }
        __syncthreads();
        float inv = sinv;

        size_t rowb = (size_t)(b * TT + t) * U2;
        for (int u = tid; u < UU; u += 256) {
            float acc = 0.f;
#pragma unroll 8
            for (int s = 0; s < SS; s++) acc = fmaf(sc[s] * inv, ob[(size_t)s * UU + u], acc);
            __nv_bfloat16 ch, cl; split1(acc, ch, cl);
            g_hcHi[rowb + u] = ch;
            g_hcLo[rowb + u] = cl;
        }
    } else {
        // ---------- LSTM gate (h -> hc bf16 hi/lo directly) ----------
        int gid = (blockIdx.x - BB) * 256 + tid;     // 0 .. B*U-1
        int b = gid >> 10, u = gid & 1023;
        const float* xd = g_Xd + (size_t)(b * TT + t) * G4;
        float z[4];
#pragma unroll
        for (int gI = 0; gI < 4; gI++) {
            int col = UU + gI * UU + u;              // z block sits after q block
#pragma unroll
            for (int ks = 0; ks < RS; ks++)
                z[gI] = (ks == 0 ? xd[gI * UU + u] : z[gI]) + g_p[((size_t)ks * BB + b) * NC + col];
        }
        float cprev = g_c[gid];
        float cn = sigf(z[1]) * cprev + sigf(z[0]) * tanhf(z[2]);
        float hn = sigf(z[3]) * tanhf(cn);
        g_c[gid] = cn;
        g_h[gid] = hn;
        __nv_bfloat16 hh, hl; split1(hn, hh, hl);
        g_hHi[gid] = hh; g_hLo[gid] = hl;
        size_t row = (size_t)(b * TT + t) * U2 + UU + u;
        g_hcHi[row] = hh;
        g_hcLo[row] = hl;
    }
}

// ---------------- launch ----------------
extern "C" void kernel_launch(void* const* d_in, const int* in_sizes, int n_in,
                              void* d_out, int out_size)
{
    const int*   x       = (const int*)d_in[0];
    const int*   y       = (const int*)d_in[1];
    const float* enc_emb = (const float*)d_in[2];
    const float* dec_emb = (const float*)d_in[3];
    const float* W_ih_e  = (const float*)d_in[4];
    const float* W_hh_e  = (const float*)d_in[5];
    const float* b_ih_e  = (const float*)d_in[6];
    const float* b_hh_e  = (const float*)d_in[7];
    const float* Wa      = (const float*)d_in[8];
    const float* ba      = (const float*)d_in[9];
    const float* W_ih_d  = (const float*)d_in[10];
    const float* W_hh_d  = (const float*)d_in[11];
    const float* b_ih_d  = (const float*)d_in[12];
    const float* b_hh_d  = (const float*)d_in[13];
    const float* Wd      = (const float*)d_in[14];
    const float* bd      = (const float*)d_in[15];
    float* out = (float*)d_out;

    float *pXe, *pXd, *pP;
    __nv_bfloat16 *pXeHi, *pXeLo, *pXdHi, *pXdLo, *pWeHi, *pWeLo, *pWidHi, *pWidLo;
    __nv_bfloat16 *pWdHi, *pWdLo, *pHcHi, *pHcLo;
    __nv_bfloat16 *pWhheHi, *pWhheLo, *pWcatHi, *pWcatLo, *pHHi, *pHLo;
    cudaGetSymbolAddress((void**)&pXe, g_Xe);
    cudaGetSymbolAddress((void**)&pXd, g_Xd);
    cudaGetSymbolAddress((void**)&pP,  g_p);
    cudaGetSymbolAddress((void**)&pXeHi, g_XembEHi);
    cudaGetSymbolAddress((void**)&pXeLo, g_XembELo);
    cudaGetSymbolAddress((void**)&pXdHi, g_XembDHi);
    cudaGetSymbolAddress((void**)&pXdLo, g_XembDLo);
    cudaGetSymbolAddress((void**)&pWeHi, g_WeHi);
    cudaGetSymbolAddress((void**)&pWeLo, g_WeLo);
    cudaGetSymbolAddress((void**)&pWidHi, g_WidHi);
    cudaGetSymbolAddress((void**)&pWidLo, g_WidLo);
    cudaGetSymbolAddress((void**)&pWdHi, g_WdHi);
    cudaGetSymbolAddress((void**)&pWdLo, g_WdLo);
    cudaGetSymbolAddress((void**)&pHcHi, g_hcHi);
    cudaGetSymbolAddress((void**)&pHcLo, g_hcLo);
    cudaGetSymbolAddress((void**)&pWhheHi, g_WhheHi);
    cudaGetSymbolAddress((void**)&pWhheLo, g_WhheLo);
    cudaGetSymbolAddress((void**)&pWcatHi, g_WcatHi);
    cudaGetSymbolAddress((void**)&pWcatLo, g_WcatLo);
    cudaGetSymbolAddress((void**)&pHHi, g_hHi);
    cudaGetSymbolAddress((void**)&pHLo, g_hLo);

    cudaFuncSetAttribute(k_hmma<0>, cudaFuncAttributeMaxDynamicSharedMemorySize, SMEM_DYN);
    cudaFuncSetAttribute(k_hmma<1>, cudaFuncAttributeMaxDynamicSharedMemorySize, SMEM_DYN);
    cudaFuncSetAttribute(k_hmma_rec, cudaFuncAttributeMaxDynamicSharedMemorySize, RSMEM_DYN);

    // embeddings + init + weight splits (split4 does 4 elems/thread -> /4 grids)
    k_gather_enc<<<BB * SS * (EE / 4) / 256, 256>>>(x, enc_emb);
    k_gather_dec<<<BB * TT * (EE / 4) / 256, 256>>>(y, dec_emb);
    k_init_state<<<BB * UU / 256, 256>>>();
    {
        int n4 = G4 * EE / 4;
        int g = (n4 / 4 + 255) / 256;
        k_split4<<<g, 256>>>((const float4*)W_ih_e,
            (__nv_bfloat162*)pWeHi, (__nv_bfloat162*)pWeLo, n4);
        k_split4<<<g, 256>>>((const float4*)W_ih_d,
            (__nv_bfloat162*)pWidHi, (__nv_bfloat162*)pWidLo, n4);
    }
    {   // recurrence weights: W_hh_e ; [Wa ; W_hh_d] concatenated
        int n4e = G4 * UU / 4;
        int ge = (n4e / 4 + 255) / 256;
        k_split4<<<ge, 256>>>((const float4*)W_hh_e,
            (__nv_bfloat162*)pWhheHi, (__nv_bfloat162*)pWhheLo, n4e);
        int n4a = UU * UU / 4;
        int ga = (n4a / 4 + 255) / 256;
        k_split4<<<ga, 256>>>((const float4*)Wa,
            (__nv_bfloat162*)pWcatHi, (__nv_bfloat162*)pWcatLo, n4a);
        int n4d = G4 * UU / 4;
        int gd = (n4d / 4 + 255) / 256;
        k_split4<<<gd, 256>>>((const float4*)W_hh_d,
            (__nv_bfloat162*)(pWcatHi + (size_t)UU * UU),
            (__nv_bfloat162*)(pWcatLo + (size_t)UU * UU), n4d);
    }
    {
        int n4 = (int)((size_t)VD_ * U2 / 4);
        int g = (n4 / 4 + 255) / 256;
        k_split4<<<g, 256>>>((const float4*)Wd,
            (__nv_bfloat162*)pWdHi, (__nv_bfloat162*)pWdLo, n4);
    }

    // time-batched input projections
    k_hmma<0><<<dim3(G4 / 128, (BB * SS) / 128), 256, SMEM_DYN>>>(
        pXeHi, pXeLo, pWeHi, pWeLo, b_ih_e, b_hh_e, pXe, BB * SS, G4, EE);
    k_hmma<0><<<dim3(G4 / 128, (BB * TT) / 128), 256, SMEM_DYN>>>(
        pXdHi, pXdLo, pWidHi, pWidLo, b_ih_d, b_hh_d, pXd, BB * TT, G4, EE);

    // encoder recurrence (tensor pipe)
    for (int t = 0; t < SS; t++) {
        k_hmma_rec<<<dim3(G4 / 128, RS), 256, RSMEM_DYN>>>(
            pHHi, pHLo, pWhheHi, pWhheLo, pP, G4);
        k_enc_gate<<<BB * UU / 256, 256>>>(t);
    }

    // decoder recurrence: one combined GEMM (q ‖ z) + one fused attn/gate kernel per step
    for (int t = 0; t < TT; t++) {
        k_hmma_rec<<<dim3(NC / 128, RS), 256, RSMEM_DYN>>>(
            pHHi, pHLo, pWcatHi, pWcatLo, pP, NC);
        k_dec_fused<<<BB + BB * UU / 256, 256>>>(t, ba);
    }

    // batched logits (A = Wd rows, B = hc rows; hc written bf16-split in the decoder)
    k_hmma<1><<<dim3((BB * TT) / 128, VD_ / 128), 256, SMEM_DYN>>>(
        pWdHi, pWdLo, pHcHi, pHcLo, bd, nullptr, out, VD_, BB * TT, U2);
}